// round 13
// baseline (speedup 1.0000x reference)
#include <cuda_runtime.h>
#include <cuda_bf16.h>
#include <cuda_fp16.h>

// ---------------- problem constants ----------------
#define Nn      12288
#define Ee      393216
#define Hh      256
#define WPR     384            // Nn/32 words per bitmap row
#define MAXNNZ  (2*Ee)
#define DOUT    128
#define NCLS    8
#define HCH     64             // D_OUT/2

// fused-kernel smem layout (in 32-bit words)
#define AS_STRIDE 148          // 148 mod 32 == 20 -> conflict-free frag loads
#define AS_WORDS  (64 * AS_STRIDE)
#define WS_WORDS  (2 * 256 * 20)
#define FUSED_SMEM_BYTES ((AS_WORDS + WS_WORDS) * 4 + 2 * 128 * 8)

// ---------------- device scratch (static, no allocation) ----------------
__device__ __align__(16) unsigned g_bmA[(size_t)Nn * WPR];   // A[i][j] bit
__device__ __align__(16) unsigned g_bmT[(size_t)Nn * WPR];   // A^T[i][j] bit
__device__ int      g_rowptr[Nn];
__device__ int      g_rowcnt[Nn];
__device__ int      g_col[MAXNNZ];
__device__ float    g_val[MAXNNZ];
__device__ __align__(16) __half g_ha[(size_t)Nn * Hh];   // activation ping
__device__ __align__(16) __half g_hb[(size_t)Nn * Hh];   // activation pong
__device__ __align__(16) __half g_neh[(size_t)Nn * DOUT];
__device__ float    g_hid[(size_t)Nn * HCH];
__device__ int      g_is64;
__device__ int      g_nnz;

__device__ __forceinline__ unsigned packh2(float a, float b) {
    __half2 h = __floats2half2_rn(a, b);
    return *(unsigned*)&h;
}

// ---------------- graph build ----------------
// int64-vs-int32 edge_index detection: if data is int64 (values < 12288),
// every odd 32-bit word (hi half) is zero. Also resets the nnz allocator.
__global__ void detect_kernel(const int* __restrict__ ei) {
    __shared__ int sh[256];
    int t = threadIdx.x;
    int v = 0;
    for (int i = t; i < 4096; i += 256) v |= ei[2 * i + 1];
    sh[t] = v; __syncthreads();
    for (int o = 128; o > 0; o >>= 1) { if (t < o) sh[t] |= sh[t + o]; __syncthreads(); }
    if (t == 0) { g_is64 = (sh[0] == 0) ? 1 : 0; g_nnz = 0; }
}

__global__ void __launch_bounds__(256) scatter_kernel(const void* __restrict__ ei_raw) {
    int base = blockIdx.x * 1024 + threadIdx.x;
    const int is64 = g_is64;
#pragma unroll
    for (int u = 0; u < 4; u++) {
        int e = base + u * 256;
        int s, d;
        if (is64) {
            const long long* ei = (const long long*)ei_raw;
            s = (int)ei[e]; d = (int)ei[Ee + e];
        } else {
            const int* ei = (const int*)ei_raw;
            s = ei[e]; d = ei[Ee + e];
        }
        atomicOr(&g_bmA[(size_t)s * WPR + (d >> 5)], 1u << (d & 31));
        atomicOr(&g_bmT[(size_t)d * WPR + (s >> 5)], 1u << (s & 31));
    }
}

// Fused count + allocate + fill + bitmap-clear: one warp per row, single pass.
// Bitmaps are zeroed right after reading, so no separate clear kernel is
// needed (they are statically zero-initialized and every call re-zeroes).
// CSR segment offsets come from a block-aggregated atomicAdd; per-row entry
// content (sorted by column) is invariant -> deterministic SpMM output.
__global__ void __launch_bounds__(256) fill2_kernel() {
    __shared__ int s_tot[8];
    __shared__ int s_base;
    const int wip  = threadIdx.x >> 5;
    const int lane = threadIdx.x & 31;
    const int row  = blockIdx.x * 8 + wip;

    uint4* pa = (uint4*)g_bmA + (size_t)row * (WPR / 4) + lane * 3;
    uint4* pt = (uint4*)g_bmT + (size_t)row * (WPR / 4) + lane * 3;
    uint4 A0 = pa[0], A1 = pa[1], A2 = pa[2];
    uint4 T0 = pt[0], T1 = pt[1], T2 = pt[2];
    const uint4 z = make_uint4(0u, 0u, 0u, 0u);
    pa[0] = z; pa[1] = z; pa[2] = z;
    pt[0] = z; pt[1] = z; pt[2] = z;
    unsigned aw[12] = {A0.x, A0.y, A0.z, A0.w, A1.x, A1.y, A1.z, A1.w,
                       A2.x, A2.y, A2.z, A2.w};
    unsigned tw[12] = {T0.x, T0.y, T0.z, T0.w, T1.x, T1.y, T1.z, T1.w,
                       T2.x, T2.y, T2.z, T2.w};
    int cu = 0, rs = 0;
#pragma unroll
    for (int i = 0; i < 12; i++) {
        cu += __popc(aw[i] | tw[i]);
        rs += __popc(aw[i]) + __popc(tw[i]);
    }
#pragma unroll
    for (int off = 16; off > 0; off >>= 1)
        rs += __shfl_xor_sync(0xFFFFFFFFu, rs, off);
    int x = cu;                               // inclusive scan of cu over lanes
#pragma unroll
    for (int off = 1; off < 32; off <<= 1) {
        int y = __shfl_up_sync(0xFFFFFFFFu, x, off);
        if (lane >= off) x += y;
    }
    int tot = __shfl_sync(0xFFFFFFFFu, x, 31);

    if (lane == 0) s_tot[wip] = tot;
    __syncthreads();
    if (threadIdx.x == 0) {
        int run = 0;
#pragma unroll
        for (int i = 0; i < 8; i++) { int v = s_tot[i]; s_tot[i] = run; run += v; }
        s_base = atomicAdd(&g_nnz, run);
    }
    __syncthreads();
    int rowbase = s_base + s_tot[wip];

    if (lane == 0) { g_rowptr[row] = rowbase; g_rowcnt[row] = tot; }
    float inv = 1.0f / ((float)rs + 1e-8f);
    int pos = rowbase + x - cu;
#pragma unroll
    for (int i = 0; i < 12; i++) {
        unsigned a = aw[i], t = tw[i], u = a | t;
        int colbase = (lane * 12 + i) * 32;
        while (u) {
            int b = __ffs(u) - 1;
            g_col[pos] = colbase + b;
            g_val[pos] = (float)(((a >> b) & 1u) + ((t >> b) & 1u)) * inv;
            ++pos;
            u &= u - 1;
        }
    }
}

// ---------------- fused SpMM + GEMM ---------------------------------------
// out = relu( (x + adj_norm @ x) @ W^T + bias ),  x fp16 [Nn,256], W fp32.
// One CTA owns 64 rows: stage 1 computes its s rows into smem (two 128-thread
// groups on alternate rows, synced with named barriers; identical per-row
// arithmetic to the standalone SpMM). Stage 2 runs a 64x256x256 HMMA GEMM
// with s resident in smem as the A operand. CTAs pipeline: gather (memory)
// of one CTA overlaps MMA (tensor) of others.
__global__ void __launch_bounds__(256, 2)
spmm_gemm(const __half* __restrict__ xh, const float* __restrict__ W,
          const float* __restrict__ bias, __half* __restrict__ Ch) {
    extern __shared__ unsigned dsm[];
    unsigned* As  = dsm;                       // [64][AS_STRIDE]
    unsigned* Ws  = dsm + AS_WORDS;            // [2][256][20]
    int*    scol  = (int*)(dsm + AS_WORDS + WS_WORDS);   // [2][128]
    float*  svalp = (float*)(scol + 256);                // [2][128]

    const int tid = threadIdx.x;
    const int b0  = blockIdx.x * 64;

    // ---- stage 1: s rows into As ----
    {
        const int wg = tid >> 7;          // 0/1: threads 0-127 / 128-255
        const int f2 = tid & 127;
        int*   mycol = scol  + wg * 128;
        float* myval = svalp + wg * 128;
        for (int r = wg; r < 64; r += 2) {
            int row = b0 + r;
            float2 acc = __half22float2(((const __half2*)(xh + (size_t)row * Hh))[f2]);
            int start = g_rowptr[row], end = start + g_rowcnt[row];
            for (int c = start; c < end; c += 128) {
                int m = end - c; if (m > 128) m = 128;
                if (f2 < m) { mycol[f2] = g_col[c + f2]; myval[f2] = g_val[c + f2]; }
                asm volatile("bar.sync %0, 128;" :: "r"(wg + 1) : "memory");
#pragma unroll 4
                for (int j = 0; j < m; ++j) {
                    float2 v = __half22float2(
                        ((const __half2*)(xh + (size_t)mycol[j] * Hh))[f2]);
                    acc.x = fmaf(myval[j], v.x, acc.x);
                    acc.y = fmaf(myval[j], v.y, acc.y);
                }
                asm volatile("bar.sync %0, 128;" :: "r"(wg + 1) : "memory");
            }
            As[r * AS_STRIDE + f2] = packh2(acc.x, acc.y);
        }
    }
    __syncthreads();   // As complete

    // ---- stage 2: GEMM, A = As (resident), W streamed in BK=32 chunks ----
    const int wid = tid >> 5, lane = tid & 31;
    const int g = lane >> 2, tig = lane & 3;

    auto lsW = [&](int it, int buf) {
        const int half = tid & 1;
        const int kbase = it * 32 + half * 16;
#pragma unroll
        for (int pass = 0; pass < 2; ++pass) {
            int rowe = (tid >> 1) + pass * 128;
            const float* wp = W + (size_t)rowe * Hh + kbase;
            float4 f0 = *(const float4*)(wp);
            float4 f1 = *(const float4*)(wp + 4);
            float4 f2_ = *(const float4*)(wp + 8);
            float4 f3 = *(const float4*)(wp + 12);
            unsigned* dst = Ws + buf * (256 * 20) + rowe * 20 + half * 8;
            *(uint4*)dst = make_uint4(packh2(f0.x, f0.y), packh2(f0.z, f0.w),
                                      packh2(f1.x, f1.y), packh2(f1.z, f1.w));
            *(uint4*)(dst + 4) = make_uint4(packh2(f2_.x, f2_.y), packh2(f2_.z, f2_.w),
                                            packh2(f3.x, f3.y), packh2(f3.z, f3.w));
        }
    };

    float acc[4][4][4];
#pragma unroll
    for (int mt = 0; mt < 4; mt++)
#pragma unroll
        for (int nt = 0; nt < 4; nt++)
#pragma unroll
            for (int i = 0; i < 4; i++) acc[mt][nt][i] = 0.0f;

    lsW(0, 0);
    __syncthreads();

    for (int it = 0; it < 8; ++it) {
        const int cur = it & 1;
        if (it < 7) lsW(it + 1, cur ^ 1);
#pragma unroll
        for (int ks = 0; ks < 2; ++ks) {
            const int kp0 = it * 16 + ks * 8;   // As word offset
            const int kw  = ks * 8;             // Ws word offset in chunk
            unsigned af[4][4];
#pragma unroll
            for (int mt = 0; mt < 4; mt++) {
                const unsigned* p = &As[(mt * 16 + g) * AS_STRIDE + kp0 + tig];
                af[mt][0] = p[0];
                af[mt][1] = p[AS_STRIDE * 8];
                af[mt][2] = p[4];
                af[mt][3] = p[AS_STRIDE * 8 + 4];
            }
            unsigned bf[4][2];
#pragma unroll
            for (int nt = 0; nt < 4; nt++) {
                const unsigned* p = &Ws[cur * (256 * 20) +
                                        (wid * 32 + nt * 8 + g) * 20 + kw + tig];
                bf[nt][0] = p[0];
                bf[nt][1] = p[4];
            }
#pragma unroll
            for (int mt = 0; mt < 4; mt++)
#pragma unroll
                for (int nt = 0; nt < 4; nt++) {
                    asm volatile(
                        "mma.sync.aligned.m16n8k16.row.col.f32.f16.f16.f32 "
                        "{%0,%1,%2,%3}, {%4,%5,%6,%7}, {%8,%9}, {%0,%1,%2,%3};"
                        : "+f"(acc[mt][nt][0]), "+f"(acc[mt][nt][1]),
                          "+f"(acc[mt][nt][2]), "+f"(acc[mt][nt][3])
                        : "r"(af[mt][0]), "r"(af[mt][1]),
                          "r"(af[mt][2]), "r"(af[mt][3]),
                          "r"(bf[nt][0]), "r"(bf[nt][1]));
                }
        }
        __syncthreads();
    }

    // epilogue: bias + relu, fp16 stores
#pragma unroll
    for (int nt = 0; nt < 4; nt++) {
        int c0 = wid * 32 + nt * 8 + 2 * tig;
        float bb0 = bias[c0], bb1 = bias[c0 + 1];
#pragma unroll
        for (int mt = 0; mt < 4; mt++) {
            int r0 = b0 + mt * 16 + g;
            float x0 = fmaxf(acc[mt][nt][0] + bb0, 0.f);
            float x1 = fmaxf(acc[mt][nt][1] + bb1, 0.f);
            float x2 = fmaxf(acc[mt][nt][2] + bb0, 0.f);
            float x3 = fmaxf(acc[mt][nt][3] + bb1, 0.f);
            *(unsigned*)(Ch + (size_t)r0 * Hh + c0) = packh2(x0, x1);
            *(unsigned*)(Ch + (size_t)(r0 + 8) * Hh + c0) = packh2(x2, x3);
        }
    }
}

// ---------------- fp16 tensor-core GEMM:  C = act(A @ W^T + bias) ----------
// A: [M,K] (fp16, or fp32 when AF32), W: [Nout,K] fp32, fp32 accumulate.
// BM=64, BN=128, BK=32, 256 thr, 8 warps (2x4), mma.m16n8k16.f16.
template <int RELU, int WF, int WH, int AF32>
__global__ void __launch_bounds__(256, 2)
hmma_gemm(const void* __restrict__ Ain, const float* __restrict__ W,
          const float* __restrict__ bias, float* __restrict__ C,
          __half* __restrict__ Ch, int M, int Nout, int K) {
    __shared__ unsigned As[2][64 * 20];    // [m][kp] stride 20 (16 + pad 4)
    __shared__ unsigned Ws[2][128 * 20];

    const int tid  = threadIdx.x;
    const int wid  = tid >> 5;
    const int lane = tid & 31;
    const int g    = lane >> 2;        // 0..7
    const int tig  = lane & 3;         // 0..3
    const int wm   = wid & 1;          // 2 warps along M (32 rows each)
    const int wn   = wid >> 1;         // 4 warps along N (32 cols each)
    const int bx = blockIdx.x, by = blockIdx.y;

    const int lr  = tid >> 2;          // 0..63
    const int kq  = (tid & 3) * 4;     // word offset 0,4,8,12
    const int kq8 = (tid & 3) * 8;     // element offset 0,8,16,24

    const __half* Ah = (const __half*)Ain;
    const float*  Af = (const float*)Ain;

    float acc[2][4][4];
#pragma unroll
    for (int mt = 0; mt < 2; mt++)
#pragma unroll
        for (int nt = 0; nt < 4; nt++)
#pragma unroll
            for (int i = 0; i < 4; i++) acc[mt][nt][i] = 0.0f;

    const size_t aRow = (size_t)(by * 64 + lr) * K;
    const int wR0 = bx * 128 + lr, wR1 = wR0 + 64;
    const bool v0 = wR0 < Nout, v1 = wR1 < Nout;
    const size_t wRow0 = (size_t)(v0 ? wR0 : 0) * K;
    const size_t wRow1 = (size_t)(v1 ? wR1 : 0) * K;
    const float4 z4 = make_float4(0.f, 0.f, 0.f, 0.f);

    const int kIter = K >> 5;
    uint4 qa, qw0, qw1;

    auto loadg = [&](int it) {
        const int koff = it * 32 + kq8;
        if (AF32) {
            float4 f0 = *(const float4*)(Af + aRow + koff);
            float4 f1 = *(const float4*)(Af + aRow + koff + 4);
            qa = make_uint4(packh2(f0.x, f0.y), packh2(f0.z, f0.w),
                            packh2(f1.x, f1.y), packh2(f1.z, f1.w));
        } else {
            qa = *(const uint4*)(Ah + aRow + koff);
        }
        float4 f0 = v0 ? *(const float4*)(W + wRow0 + koff) : z4;
        float4 f1 = v0 ? *(const float4*)(W + wRow0 + koff + 4) : z4;
        qw0 = make_uint4(packh2(f0.x, f0.y), packh2(f0.z, f0.w),
                         packh2(f1.x, f1.y), packh2(f1.z, f1.w));
        f0 = v1 ? *(const float4*)(W + wRow1 + koff) : z4;
        f1 = v1 ? *(const float4*)(W + wRow1 + koff + 4) : z4;
        qw1 = make_uint4(packh2(f0.x, f0.y), packh2(f0.z, f0.w),
                         packh2(f1.x, f1.y), packh2(f1.z, f1.w));
    };
    auto stos = [&](int b) {
        *(uint4*)&As[b][lr * 20 + kq]        = qa;
        *(uint4*)&Ws[b][lr * 20 + kq]        = qw0;
        *(uint4*)&Ws[b][(lr + 64) * 20 + kq] = qw1;
    };

    loadg(0);
    stos(0);
    __syncthreads();

    for (int it = 0; it < kIter; ++it) {
        const int cur = it & 1;
        if (it + 1 < kIter) loadg(it + 1);
#pragma unroll
        for (int ks = 0; ks < 2; ++ks) {        // two k16 steps per BK=32
            const int kp0 = ks * 8;
            unsigned af[2][4];
#pragma unroll
            for (int mt = 0; mt < 2; mt++) {
                int m = wm * 32 + mt * 16 + g;
                const unsigned* p = &As[cur][m * 20 + kp0 + tig];
                af[mt][0] = p[0];
                af[mt][1] = p[160];
                af[mt][2] = p[4];
                af[mt][3] = p[164];
            }
            unsigned bf[4][2];
#pragma unroll
            for (int nt = 0; nt < 4; nt++) {
                int n = wn * 32 + nt * 8 + g;
                const unsigned* p = &Ws[cur][n * 20 + kp0 + tig];
                bf[nt][0] = p[0];
                bf[nt][1] = p[4];
            }
#pragma unroll
            for (int mt = 0; mt < 2; mt++)
#pragma unroll
                for (int nt = 0; nt < 4; nt++) {
                    asm volatile(
                        "mma.sync.aligned.m16n8k16.row.col.f32.f16.f16.f32 "
                        "{%0,%1,%2,%3}, {%4,%5,%6,%7}, {%8,%9}, {%0,%1,%2,%3};"
                        : "+f"(acc[mt][nt][0]), "+f"(acc[mt][nt][1]),
                          "+f"(acc[mt][nt][2]), "+f"(acc[mt][nt][3])
                        : "r"(af[mt][0]), "r"(af[mt][1]),
                          "r"(af[mt][2]), "r"(af[mt][3]),
                          "r"(bf[nt][0]), "r"(bf[nt][1]));
                }
        }
        if (it + 1 < kIter) {
            stos((it + 1) & 1);
            __syncthreads();
        }
    }

    // epilogue: bias + optional relu; fp32 and/or fp16 stores
    const int rBase = by * 64 + wm * 32;
    const int cBase = bx * 128 + wn * 32;
#pragma unroll
    for (int nt = 0; nt < 4; nt++) {
        int c0 = cBase + nt * 8 + 2 * tig;
        if (c0 < Nout) {
            float b0 = bias[c0], b1 = bias[c0 + 1];
#pragma unroll
            for (int mt = 0; mt < 2; mt++) {
                int r0 = rBase + mt * 16 + g;
                float x0 = acc[mt][nt][0] + b0;
                float x1 = acc[mt][nt][1] + b1;
                float x2 = acc[mt][nt][2] + b0;
                float x3 = acc[mt][nt][3] + b1;
                if (RELU) {
                    x0 = fmaxf(x0, 0.f); x1 = fmaxf(x1, 0.f);
                    x2 = fmaxf(x2, 0.f); x3 = fmaxf(x3, 0.f);
                }
                if (WF) {
                    *(float2*)(C + (size_t)r0 * Nout + c0) = make_float2(x0, x1);
                    *(float2*)(C + (size_t)(r0 + 8) * Nout + c0) = make_float2(x2, x3);
                }
                if (WH) {
                    *(unsigned*)(Ch + (size_t)r0 * Nout + c0) = packh2(x0, x1);
                    *(unsigned*)(Ch + (size_t)(r0 + 8) * Nout + c0) = packh2(x2, x3);
                }
            }
        }
    }
}

// ---------------- classifier tail:  hl = hid @ hc_w2^T + b2 ----------------
__global__ void __launch_bounds__(256) hc2_kernel(const float* __restrict__ hid,
                                                  const float* __restrict__ w2,
                                                  const float* __restrict__ b2,
                                                  float* __restrict__ out) {
    __shared__ float sw[NCLS * HCH];
    int t = threadIdx.x;
    for (int i = t; i < NCLS * HCH; i += 256) sw[i] = w2[i];
    __syncthreads();
    int g = blockIdx.x * 256 + t;
    int n = g >> 3, c = g & 7;
    float acc = b2[c];
    const float* hrow = hid + (size_t)n * HCH;
    const float* wrow = sw + c * HCH;
#pragma unroll 8
    for (int k = 0; k < HCH; ++k) acc = fmaf(hrow[k], wrow[k], acc);
    out[g] = acc;
}

// ---------------- column mean of node_embeddings ----------------
__global__ void __launch_bounds__(256) mean_kernel(const float* __restrict__ ne,
                                                   float* __restrict__ out) {
    int f = blockIdx.x;        // 0..127
    int t = threadIdx.x;
    float acc = 0.0f;
    for (int r = t; r < Nn; r += 256) acc += ne[(size_t)r * DOUT + f];
    __shared__ float sh[256];
    sh[t] = acc; __syncthreads();
    for (int o = 128; o > 0; o >>= 1) { if (t < o) sh[t] += sh[t + o]; __syncthreads(); }
    if (t == 0) out[f] = sh[0] * (1.0f / (float)Nn);
}

// ---------------- streams/events/attrs (once at static init) ---------------
struct AuxRes {
    cudaStream_t s = nullptr;
    cudaEvent_t fork1 = nullptr, join1 = nullptr, fork2 = nullptr, join2 = nullptr;
    bool ok = false;
    AuxRes() {
        ok = (cudaStreamCreateWithFlags(&s, cudaStreamNonBlocking) == cudaSuccess)
          && (cudaEventCreateWithFlags(&fork1, cudaEventDisableTiming) == cudaSuccess)
          && (cudaEventCreateWithFlags(&join1, cudaEventDisableTiming) == cudaSuccess)
          && (cudaEventCreateWithFlags(&fork2, cudaEventDisableTiming) == cudaSuccess)
          && (cudaEventCreateWithFlags(&join2, cudaEventDisableTiming) == cudaSuccess);
        cudaFuncSetAttribute(spmm_gemm,
                             cudaFuncAttributeMaxDynamicSharedMemorySize,
                             FUSED_SMEM_BYTES);
    }
};
static AuxRes g_aux;

// ---------------- launch ----------------
extern "C" void kernel_launch(void* const* d_in, const int* in_sizes, int n_in,
                              void* d_out, int out_size) {
    const float* X     = (const float*)d_in[0];
    const void*  EI    = d_in[1];
    const float* enc_w1 = (const float*)d_in[2];
    const float* enc_b1 = (const float*)d_in[3];
    const float* enc_w2 = (const float*)d_in[4];
    const float* enc_b2 = (const float*)d_in[5];
    const float* gin_w  = (const float*)d_in[6];
    const float* gin_b  = (const float*)d_in[7];
    const float* gl_w   = (const float*)d_in[8];
    const float* gl_b   = (const float*)d_in[9];
    const float* gout_w = (const float*)d_in[10];
    const float* gout_b = (const float*)d_in[11];
    const float* proj_w = (const float*)d_in[12];
    const float* proj_b = (const float*)d_in[13];
    const float* hc_w1  = (const float*)d_in[14];
    const float* hc_b1  = (const float*)d_in[15];
    const float* hc_w2  = (const float*)d_in[16];
    const float* hc_b2  = (const float*)d_in[17];

    __half *hA, *hB, *neh;
    float *hid;
    cudaGetSymbolAddress((void**)&hA, g_ha);
    cudaGetSymbolAddress((void**)&hB, g_hb);
    cudaGetSymbolAddress((void**)&neh, g_neh);
    cudaGetSymbolAddress((void**)&hid, g_hid);

    float* out = (float*)d_out;
    float* ne = out;                       // [Nn, 128]
    float* hl = out + (size_t)Nn * DOUT;   // [Nn, 8]
    float* gf = hl + (size_t)Nn * NCLS;    // [128]

    const bool fork = g_aux.ok;
    cudaStream_t sb = fork ? g_aux.s : (cudaStream_t)0;   // build stream

    // --- graph build (aux stream, overlapped with encoder) ---
    if (fork) {
        cudaEventRecord(g_aux.fork1, 0);
        cudaStreamWaitEvent(sb, g_aux.fork1, 0);
    }
    detect_kernel<<<1, 256, 0, sb>>>((const int*)EI);
    scatter_kernel<<<Ee / 1024, 256, 0, sb>>>(EI);
    fill2_kernel<<<Nn / 8, 256, 0, sb>>>();
    if (fork) cudaEventRecord(g_aux.join1, sb);

    dim3 g256(2, Nn / 64);    // Nout=256
    dim3 g128(1, Nn / 64);    // Nout<=128

    // --- encoder (default stream, overlaps graph build) ---
    hmma_gemm<1,0,1,1><<<g256, 256>>>(X,  enc_w1, enc_b1, nullptr, hA, Nn, Hh, 256);
    hmma_gemm<0,0,1,0><<<g256, 256>>>(hA, enc_w2, enc_b2, nullptr, hB, Nn, Hh, Hh);
    hmma_gemm<1,0,1,0><<<g256, 256>>>(hB, gin_w,  gin_b,  nullptr, hA, Nn, Hh, Hh);

    if (fork) cudaStreamWaitEvent(0, g_aux.join1, 0);  // join: CSR ready

    // --- 3 fused message-passing layers (SpMM + GEMM in one kernel) ---
    spmm_gemm<<<Nn / 64, 256, FUSED_SMEM_BYTES>>>(hA, gl_w,               gl_b,          hB);
    spmm_gemm<<<Nn / 64, 256, FUSED_SMEM_BYTES>>>(hB, gl_w + (size_t)Hh * Hh,   gl_b + Hh,     hA);
    spmm_gemm<<<Nn / 64, 256, FUSED_SMEM_BYTES>>>(hA, gl_w + (size_t)2 * Hh * Hh, gl_b + 2 * Hh, hB);

    // output proj
    hmma_gemm<0,0,1,0><<<g256, 256>>>(hB, gout_w, gout_b, nullptr, hA, Nn, Hh, Hh);
    // node embeddings: fp32 to d_out + fp16 shadow for classifier
    hmma_gemm<1,1,1,0><<<g128, 256>>>(hA, proj_w, proj_b, ne, neh, Nn, DOUT, Hh);

    // --- tail: mean on aux stream concurrent with classifier ---
    if (fork) {
        cudaEventRecord(g_aux.fork2, 0);
        cudaStreamWaitEvent(sb, g_aux.fork2, 0);
    }
    mean_kernel<<<DOUT, 256, 0, sb>>>(ne, gf);
    if (fork) cudaEventRecord(g_aux.join2, sb);

    hmma_gemm<1,1,0,0><<<g128, 256>>>(neh, hc_w1, hc_b1, hid, nullptr, Nn, HCH, DOUT);
    hc2_kernel<<<(Nn * NCLS) / 256, 256>>>(hid, hc_w2, hc_b2, hl);

    if (fork) cudaStreamWaitEvent(0, g_aux.join2, 0);
}